// round 14
// baseline (speedup 1.0000x reference)
#include <cuda_runtime.h>
#include <cfloat>

#define BATCH 8
#define NPT   1024
#define KNN   20
#define EPSV  1e-6f
#define CTOT  169   // 21+21+42+85 concat channels
#define MAXCOUT 85
#define TOTPT (BATCH * NPT)

typedef unsigned long long u64;

// ---- packed f32x2 helpers (sm_10x FFMA2) ----
__device__ __forceinline__ u64 pk2(float lo, float hi) {
    u64 r; asm("mov.b64 %0,{%1,%2};" : "=l"(r) : "f"(lo), "f"(hi)); return r;
}
__device__ __forceinline__ void fma2(u64& d, u64 a, u64 b) {
    asm("fma.rn.f32x2 %0,%1,%2,%0;" : "+l"(d) : "l"(a), "l"(b));
}
__device__ __forceinline__ float2 up2(u64 v) {
    float2 r; asm("mov.b64 {%0,%1},%2;" : "=f"(r.x), "=f"(r.y) : "l"(v)); return r;
}
// monotone float -> uint (order-preserving)
__device__ __forceinline__ unsigned ford(float v) {
    unsigned u = __float_as_uint(v);
    return (u & 0x80000000u) ? ~u : (u | 0x80000000u);
}

// -------- scratch (no allocations allowed) --------
__device__ float  g_feat[BATCH * CTOT * 3 * NPT];        // [B][169][3][N]
__device__ int    g_idx[BATCH * NPT * KNN];
__device__ float4 g_ypA[TOTPT * MAXCOUT];                // [pt][o] {p0,d0,p1,d1}
__device__ float2 g_ypB[TOTPT * MAXCOUT];                // [pt][o] {p2,d2}
__device__ float2 g_cmb[BATCH * NPT * MAXCOUT * 3];      // [pt][o][f] {pc-yf, dc-yd}
__device__ float  g_pd [BATCH * 342 * 3 * NPT];          // partial final sums

// ================= knn (fused xx) + warp-parallel top-k =================
// key_j = 2*dot(xi,xj) - xx_j  (row-constant xx_i dropped; ranking unchanged)
// TI=32 rows/block, 512 threads in two 256-thread halves (rowpairs 0-7 / 8-15),
// j-tile=4 with distance-2 register prefetch. Halves share LDG lines (L1 hit)
// => per-block L2 traffic halves vs TI=16.
template <int D>
__global__ __launch_bounds__(512, 1)
void knn_kernel(const float* __restrict__ cur, int Ctot, int coff)
{
    const int TI = 32;
    extern __shared__ float smraw[];
    float (*sdist)[NPT] = (float(*)[NPT])smraw;           // [TI][NPT] = 128 KB
    u64   (*sxp)[16]    = (u64(*)[16])(smraw + TI * NPT); // [D][16] query rowpairs

    int b  = blockIdx.x / (NPT / TI);
    int i0 = (blockIdx.x % (NPT / TI)) * TI;
    int tid = threadIdx.x;
    const float* base = cur + (size_t)(b * Ctot + coff) * 3 * NPT;

    for (int f = tid; f < D; f += 512) {
        #pragma unroll
        for (int rp = 0; rp < 16; rp++) {
            float qa = base[f * NPT + i0 + 2 * rp];
            float qb = base[f * NPT + i0 + 2 * rp + 1];
            sxp[f][rp] = pk2(qa, qb);
        }
    }
    __syncthreads();

    // ---- distance phase: half h covers rowpairs 8h..8h+7; 4 contiguous j/thread ----
    {
        int half = tid >> 8;                 // 0 or 1
        int rbase = half * 8;
        int j0 = (tid & 255) * 4;
        const float* bp = base + j0;
        u64 acc[8][4];
        float xx[4] = {0.f, 0.f, 0.f, 0.f};
        #pragma unroll
        for (int rp = 0; rp < 8; rp++)
            #pragma unroll
            for (int jj = 0; jj < 4; jj++) acc[rp][jj] = 0ull;

        float4 xv0 = *(const float4*)bp;
        float4 xv1 = *(const float4*)(bp + (D > 1 ? NPT : 0));

        #pragma unroll 2
        for (int f = 0; f < D; f++) {
            int fn = f + 2 < D ? f + 2 : D - 1;
            float4 nxt = *(const float4*)(bp + (size_t)fn * NPT);

            float4 xv = xv0;
            u64 xp0 = pk2(xv.x, xv.x), xp1 = pk2(xv.y, xv.y);
            u64 xp2 = pk2(xv.z, xv.z), xp3 = pk2(xv.w, xv.w);
            u64 q[8];
            #pragma unroll
            for (int rp = 0; rp < 8; rp++) q[rp] = sxp[f][rbase + rp];
            #pragma unroll
            for (int rp = 0; rp < 8; rp++) {
                fma2(acc[rp][0], q[rp], xp0);
                fma2(acc[rp][1], q[rp], xp1);
                fma2(acc[rp][2], q[rp], xp2);
                fma2(acc[rp][3], q[rp], xp3);
            }
            xx[0] = fmaf(xv.x, xv.x, xx[0]);
            xx[1] = fmaf(xv.y, xv.y, xx[1]);
            xx[2] = fmaf(xv.z, xv.z, xx[2]);
            xx[3] = fmaf(xv.w, xv.w, xx[3]);

            xv0 = xv1; xv1 = nxt;
        }
        #pragma unroll
        for (int rp = 0; rp < 8; rp++) {
            int arp = rbase + rp;
            float4 lo, hi;
            float2 v0 = up2(acc[rp][0]), v1 = up2(acc[rp][1]);
            float2 v2 = up2(acc[rp][2]), v3 = up2(acc[rp][3]);
            lo.x = 2.f * v0.x - xx[0]; hi.x = 2.f * v0.y - xx[0];
            lo.y = 2.f * v1.x - xx[1]; hi.y = 2.f * v1.y - xx[1];
            lo.z = 2.f * v2.x - xx[2]; hi.z = 2.f * v2.y - xx[2];
            lo.w = 2.f * v3.x - xx[3]; hi.w = 2.f * v3.y - xx[3];
            *(float4*)&sdist[2 * arp][j0]     = lo;
            *(float4*)&sdist[2 * arp + 1][j0] = hi;
        }
    }
    __syncthreads();

    // ---- top-k: warp w (0..15) handles rows 2w, 2w+1 with interleaved chains ----
    int w = tid >> 5, lane = tid & 31;
    float* row0 = sdist[2 * w];
    float* row1 = sdist[2 * w + 1];
    int ob0 = (b * NPT + i0 + 2 * w) * KNN;
    int ob1 = ob0 + KNN;

    unsigned ck0, ck1; int ci0, ci1;
    {
        float lb0 = -FLT_MAX, lb1 = -FLT_MAX;
        int li0 = 0x7fffffff, li1 = 0x7fffffff;
        #pragma unroll 8
        for (int t = 0; t < 32; t++) {
            float v0 = row0[lane + 32 * t];
            float v1 = row1[lane + 32 * t];
            if (v0 > lb0) { lb0 = v0; li0 = lane + 32 * t; }
            if (v1 > lb1) { lb1 = v1; li1 = lane + 32 * t; }
        }
        ck0 = ford(lb0); ci0 = li0;
        ck1 = ford(lb1); ci1 = li1;
    }
    for (int it = 0; it < KNN; it++) {
        unsigned mx0 = __reduce_max_sync(0xffffffffu, ck0);
        unsigned mx1 = __reduce_max_sync(0xffffffffu, ck1);
        int wb0 = __reduce_min_sync(0xffffffffu, (ck0 == mx0) ? ci0 : 0x7fffffff);
        int wb1 = __reduce_min_sync(0xffffffffu, (ck1 == mx1) ? ci1 : 0x7fffffff);
        if (lane == 0) { g_idx[ob0 + it] = wb0; g_idx[ob1 + it] = wb1; }
        int own0 = wb0 & 31, own1 = wb1 & 31;
        if (lane == (wb0 >> 5)) row0[wb0] = -FLT_MAX;
        if (lane == (wb1 >> 5)) row1[wb1] = -FLT_MAX;
        float v0 = row0[own0 + 32 * lane];
        float v1 = row1[own1 + 32 * lane];
        unsigned k0 = ford(v0), k1 = ford(v1);
        unsigned m0 = __reduce_max_sync(0xffffffffu, k0);
        unsigned m1 = __reduce_max_sync(0xffffffffu, k1);
        int r0 = __reduce_min_sync(0xffffffffu, (k0 == m0) ? (own0 + 32 * lane) : 0x7fffffff);
        int r1 = __reduce_min_sync(0xffffffffu, (k1 == m1) ? (own1 + 32 * lane) : 0x7fffffff);
        if (lane == own0) { ck0 = m0; ci0 = r0; }
        if (lane == own1) { ck1 = m1; ci1 = r1; }
    }
}

// ================= per-point linear maps =================
template <int CIN, int COUT>
__global__ void ymap_kernel(const float* __restrict__ cur, int Ctot, int coff,
                            const float* __restrict__ Wf, const float* __restrict__ Wd)
{
    const int IN2 = 2 * CIN;
    extern __shared__ float sm[];
    float4* sW = (float4*)sm;                 // [CIN][COUT] {wfL,wdL,wfR,wdR}
    float*  sx = sm + 4 * CIN * COUT;         // [3*CIN][32]

    int tid = threadIdx.x;
    int nn = tid & 31, og = tid >> 5;
    int pt0 = blockIdx.x * 32;
    int b = pt0 >> 10, n0 = pt0 & (NPT - 1);
    const float* base = cur + (size_t)(b * Ctot + coff) * 3 * NPT;

    for (int t = tid; t < CIN * COUT; t += blockDim.x) {
        int c = t / COUT, o = t - c * COUT;
        sW[t] = make_float4(Wf[o * IN2 + c], Wd[o * IN2 + c],
                            Wf[o * IN2 + CIN + c], Wd[o * IN2 + CIN + c]);
    }
    for (int t = tid; t < 3 * CIN * 32; t += blockDim.x) {
        int row = t >> 5, col = t & 31;
        sx[t] = base[row * NPT + n0 + col];
    }
    __syncthreads();

    int pt = pt0 + nn;
    for (int o = og; o < COUT; o += 8) {
        u64 accL0 = 0ull, accL1 = 0ull, accL2 = 0ull;
        u64 accR0 = 0ull, accR1 = 0ull, accR2 = 0ull;
        for (int c = 0; c < CIN; c++) {
            float4 w = sW[c * COUT + o];
            u64 wl = pk2(w.x, w.y);
            u64 wr = pk2(w.z, w.w);
            float x0 = sx[(c * 3 + 0) * 32 + nn];
            float x1 = sx[(c * 3 + 1) * 32 + nn];
            float x2 = sx[(c * 3 + 2) * 32 + nn];
            u64 p0 = pk2(x0, x0), p1 = pk2(x1, x1), p2 = pk2(x2, x2);
            fma2(accL0, wl, p0); fma2(accR0, wr, p0);
            fma2(accL1, wl, p1); fma2(accR1, wr, p1);
            fma2(accL2, wl, p2); fma2(accR2, wr, p2);
        }
        float2 l0 = up2(accL0), l1 = up2(accL1), l2 = up2(accL2);
        float2 r0 = up2(accR0), r1 = up2(accR1), r2 = up2(accR2);
        g_ypA[(size_t)pt * COUT + o] = make_float4(l0.x, l0.y, l1.x, l1.y);
        g_ypB[(size_t)pt * COUT + o] = make_float2(l2.x, l2.y);
        float2* co = g_cmb + ((size_t)pt * COUT + o) * 3;
        co[0] = make_float2(r0.x - l0.x, r0.y - l0.y);
        co[1] = make_float2(r1.x - l1.x, r1.y - l1.y);
        co[2] = make_float2(r2.x - l2.x, r2.y - l2.y);
    }
}

// ================= gather + leaky combine + mean over k =================
template <int COUT, int P, int TPB>
__global__ void pair_kernel(int ooff)
{
    __shared__ int sidx[P][KNN];
    int tid = threadIdx.x;
    int pt0 = blockIdx.x * P;

    for (int t = tid; t < P * KNN; t += TPB) {
        int p = t / KNN;
        if (pt0 + p < TOTPT) sidx[p][t - p * KNN] = g_idx[(pt0 + p) * KNN + (t - p * KNN)];
    }
    __syncthreads();

    int ln = tid / COUT, o = tid - ln * COUT;
    int pt = pt0 + ln;
    if (ln >= P || pt >= TOTPT) return;
    int b = pt >> 10, n = pt & (NPT - 1);

    const float2* cmb = g_cmb + ((size_t)pt * COUT + o) * 3;
    float2 c0 = cmb[0], c1 = cmb[1], c2 = cmb[2];

    float a0 = 0.f, a1 = 0.f, a2 = 0.f;
    #pragma unroll 5
    for (int j = 0; j < KNN; j++) {
        int nj = sidx[ln][j];
        size_t yi = ((size_t)(b << 10) + nj) * COUT + o;
        float4 A  = g_ypA[yi];
        float2 Bv = g_ypB[yi];
        float P0 = A.x  + c0.x, D0 = A.y  + c0.y;
        float P1 = A.z  + c1.x, D1 = A.w  + c1.y;
        float P2 = Bv.x + c2.x, D2 = Bv.y + c2.y;
        float dot = P0 * D0 + P1 * D1 + P2 * D2;
        float dsq = D0 * D0 + D1 * D1 + D2 * D2;
        float s = dot / (dsq + EPSV);
        float s0, s1, s2;
        if (dot >= 0.f) { s0 = P0; s1 = P1; s2 = P2; }
        else { s0 = P0 - s * D0; s1 = P1 - s * D1; s2 = P2 - s * D2; }
        a0 += 0.2f * P0 + 0.8f * s0;
        a1 += 0.2f * P1 + 0.8f * s1;
        a2 += 0.2f * P2 + 0.8f * s2;
    }
    const float invK = 1.f / KNN;
    float* fo = g_feat + (((size_t)b * CTOT + ooff + o) * 3) * NPT + n;
    fo[0 * NPT] = a0 * invK;
    fo[1 * NPT] = a1 * invK;
    fo[2 * NPT] = a2 * invK;
}

// ========== final VN layer, part 1: partial sums over c in [0,84) ==========
__global__ void final_part(const float* __restrict__ Wf, const float* __restrict__ Wd)
{
    const int OT = 11, CI = CTOT, CP = 84;
    __shared__ u64 sWfp[OT * CP];
    __shared__ u64 sWdp[CP];
    int b  = blockIdx.x / 31;
    int o0 = (blockIdx.x % 31) * OT;
    int tid = threadIdx.x;

    for (int t = tid; t < OT * CP; t += 256) {
        int o = t / CP, c = t - o * CP;
        float w = Wf[(o0 + o) * CI + c];
        sWfp[t] = pk2(w, w);
    }
    for (int t = tid; t < CP; t += 256) { float w = Wd[t]; sWdp[t] = pk2(w, w); }
    __syncthreads();

    const float* fb = g_feat + (size_t)b * CTOT * 3 * NPT;
    float* pb = g_pd + (size_t)b * 342 * 3 * NPT;
    for (int it = 0; it < 2; it++) {
        int n = 2 * (tid + it * 256);
        u64 p0[OT], p1[OT], p2[OT];
        u64 d0 = 0ull, d1 = 0ull, d2 = 0ull;
        #pragma unroll
        for (int o = 0; o < OT; o++) { p0[o] = p1[o] = p2[o] = 0ull; }

        for (int c = 0; c < CP; c++) {
            u64 x0 = *(const u64*)(fb + (c * 3 + 0) * NPT + n);
            u64 x1 = *(const u64*)(fb + (c * 3 + 1) * NPT + n);
            u64 x2 = *(const u64*)(fb + (c * 3 + 2) * NPT + n);
            u64 wd = sWdp[c];
            fma2(d0, wd, x0); fma2(d1, wd, x1); fma2(d2, wd, x2);
            #pragma unroll
            for (int o = 0; o < OT; o++) {
                u64 wf = sWfp[o * CP + c];
                fma2(p0[o], wf, x0); fma2(p1[o], wf, x1); fma2(p2[o], wf, x2);
            }
        }
        #pragma unroll
        for (int o = 0; o < OT; o++) {
            *(u64*)&pb[((o0 + o) * 3 + 0) * NPT + n] = p0[o];
            *(u64*)&pb[((o0 + o) * 3 + 1) * NPT + n] = p1[o];
            *(u64*)&pb[((o0 + o) * 3 + 2) * NPT + n] = p2[o];
        }
        if (o0 == 0) {
            *(u64*)&pb[(341 * 3 + 0) * NPT + n] = d0;
            *(u64*)&pb[(341 * 3 + 1) * NPT + n] = d1;
            *(u64*)&pb[(341 * 3 + 2) * NPT + n] = d2;
        }
    }
}

// ========== final VN layer, part 2: c in [84,169), leaky + mean over N ==========
__global__ void final_rest(const float* __restrict__ Wf, const float* __restrict__ Wd,
                           float* __restrict__ out)
{
    const int OT = 11, CI = CTOT, CP = 84, CR = CI - CP;   // 85
    __shared__ u64   sWfp[OT * CR];
    __shared__ u64   sWdp[CR];
    __shared__ float sacc[OT * 3];
    int b  = blockIdx.x / 31;
    int o0 = (blockIdx.x % 31) * OT;
    int tid = threadIdx.x;

    for (int t = tid; t < OT * CR; t += 256) {
        int o = t / CR, c = t - o * CR;
        float w = Wf[(o0 + o) * CI + CP + c];
        sWfp[t] = pk2(w, w);
    }
    for (int t = tid; t < CR; t += 256) { float w = Wd[CP + t]; sWdp[t] = pk2(w, w); }
    if (tid < OT * 3) sacc[tid] = 0.f;
    __syncthreads();

    float sum[OT][3];
    #pragma unroll
    for (int o = 0; o < OT; o++) { sum[o][0] = sum[o][1] = sum[o][2] = 0.f; }

    const float* fb = g_feat + (size_t)b * CTOT * 3 * NPT;
    const float* pb = g_pd + (size_t)b * 342 * 3 * NPT;
    for (int it = 0; it < 2; it++) {
        int n = 2 * (tid + it * 256);
        u64 p0[OT], p1[OT], p2[OT];
        #pragma unroll
        for (int o = 0; o < OT; o++) {
            p0[o] = *(const u64*)&pb[((o0 + o) * 3 + 0) * NPT + n];
            p1[o] = *(const u64*)&pb[((o0 + o) * 3 + 1) * NPT + n];
            p2[o] = *(const u64*)&pb[((o0 + o) * 3 + 2) * NPT + n];
        }
        u64 d0 = *(const u64*)&pb[(341 * 3 + 0) * NPT + n];
        u64 d1 = *(const u64*)&pb[(341 * 3 + 1) * NPT + n];
        u64 d2 = *(const u64*)&pb[(341 * 3 + 2) * NPT + n];

        for (int c = 0; c < CR; c++) {
            u64 x0 = *(const u64*)(fb + ((CP + c) * 3 + 0) * NPT + n);
            u64 x1 = *(const u64*)(fb + ((CP + c) * 3 + 1) * NPT + n);
            u64 x2 = *(const u64*)(fb + ((CP + c) * 3 + 2) * NPT + n);
            u64 wd = sWdp[c];
            fma2(d0, wd, x0); fma2(d1, wd, x1); fma2(d2, wd, x2);
            #pragma unroll
            for (int o = 0; o < OT; o++) {
                u64 wf = sWfp[o * CR + c];
                fma2(p0[o], wf, x0); fma2(p1[o], wf, x1); fma2(p2[o], wf, x2);
            }
        }
        float2 D0 = up2(d0), D1 = up2(d1), D2 = up2(d2);
        float invA = 1.f / (D0.x * D0.x + D1.x * D1.x + D2.x * D2.x + EPSV);
        float invB = 1.f / (D0.y * D0.y + D1.y * D1.y + D2.y * D2.y + EPSV);
        #pragma unroll
        for (int o = 0; o < OT; o++) {
            float2 P0 = up2(p0[o]), P1 = up2(p1[o]), P2 = up2(p2[o]);
            {
                float dot = P0.x * D0.x + P1.x * D1.x + P2.x * D2.x;
                float s0, s1, s2;
                if (dot >= 0.f) { s0 = P0.x; s1 = P1.x; s2 = P2.x; }
                else {
                    float sc = dot * invA;
                    s0 = P0.x - sc * D0.x; s1 = P1.x - sc * D1.x; s2 = P2.x - sc * D2.x;
                }
                sum[o][0] += 0.2f * P0.x + 0.8f * s0;
                sum[o][1] += 0.2f * P1.x + 0.8f * s1;
                sum[o][2] += 0.2f * P2.x + 0.8f * s2;
            }
            {
                float dot = P0.y * D0.y + P1.y * D1.y + P2.y * D2.y;
                float s0, s1, s2;
                if (dot >= 0.f) { s0 = P0.y; s1 = P1.y; s2 = P2.y; }
                else {
                    float sc = dot * invB;
                    s0 = P0.y - sc * D0.y; s1 = P1.y - sc * D1.y; s2 = P2.y - sc * D2.y;
                }
                sum[o][0] += 0.2f * P0.y + 0.8f * s0;
                sum[o][1] += 0.2f * P1.y + 0.8f * s1;
                sum[o][2] += 0.2f * P2.y + 0.8f * s2;
            }
        }
    }
    #pragma unroll
    for (int o = 0; o < OT; o++)
        #pragma unroll
        for (int dd = 0; dd < 3; dd++) {
            float v = sum[o][dd];
            #pragma unroll
            for (int s = 16; s; s >>= 1) v += __shfl_down_sync(0xffffffffu, v, s);
            if ((tid & 31) == 0) atomicAdd(&sacc[o * 3 + dd], v);
        }
    __syncthreads();
    if (tid < OT * 3) out[b * 1023 + o0 * 3 + tid] = sacc[tid] * (1.f / NPT);
}

// ================= launch =================
static constexpr size_t ymap_smem(int CIN, int COUT)
{
    return (size_t)(4 * CIN * COUT + 3 * CIN * 32) * 4;
}
static constexpr size_t knn_smem(int D)
{
    return (size_t)32 * NPT * 4 + (size_t)D * 16 * 8;
}

extern "C" void kernel_launch(void* const* d_in, const int* in_sizes, int n_in,
                              void* d_out, int out_size)
{
    const float* x   = (const float*)d_in[0];
    const float* Wf0 = (const float*)d_in[1];
    const float* Wd0 = (const float*)d_in[2];
    const float* Wf1 = (const float*)d_in[3];
    const float* Wd1 = (const float*)d_in[4];
    const float* Wf2 = (const float*)d_in[5];
    const float* Wd2 = (const float*)d_in[6];
    const float* Wf3 = (const float*)d_in[7];
    const float* Wd3 = (const float*)d_in[8];
    const float* Wf4 = (const float*)d_in[9];
    const float* Wd4 = (const float*)d_in[10];
    float* out = (float*)d_out;

    float* feat = nullptr;
    cudaGetSymbolAddress((void**)&feat, g_feat);

    static cudaStream_t s1;
    static cudaEvent_t evF, evJ;
    static bool init_done = false;
    if (!init_done) {
        cudaStreamCreateWithFlags(&s1, cudaStreamNonBlocking);
        cudaEventCreateWithFlags(&evF, cudaEventDisableTiming);
        cudaEventCreateWithFlags(&evJ, cudaEventDisableTiming);
        cudaFuncSetAttribute(ymap_kernel<42, 85>,
                             cudaFuncAttributeMaxDynamicSharedMemorySize,
                             (int)ymap_smem(42, 85));
        cudaFuncSetAttribute(knn_kernel<3>,
                             cudaFuncAttributeMaxDynamicSharedMemorySize,
                             (int)knn_smem(3));
        cudaFuncSetAttribute(knn_kernel<63>,
                             cudaFuncAttributeMaxDynamicSharedMemorySize,
                             (int)knn_smem(63));
        cudaFuncSetAttribute(knn_kernel<126>,
                             cudaFuncAttributeMaxDynamicSharedMemorySize,
                             (int)knn_smem(126));
        init_done = true;
    }

    const int KNNG = BATCH * (NPT / 32);     // 256
    const int YG   = TOTPT / 32;             // 256

    // ---- layer 0 : CIN=1, D=3, out=21 -> feat[0:21) ----
    cudaEventRecord(evF, 0);
    cudaStreamWaitEvent(s1, evF, 0);
    ymap_kernel<1, 21><<<YG, 256, ymap_smem(1, 21), s1>>>(x, 1, 0, Wf0, Wd0);
    cudaEventRecord(evJ, s1);
    knn_kernel<3><<<KNNG, 512, knn_smem(3)>>>(x, 1, 0);
    cudaStreamWaitEvent(0, evJ, 0);
    pair_kernel<21, 12, 256><<<(TOTPT + 11) / 12, 256>>>(0);

    // ---- layer 1 : CIN=21, D=63, out=21 -> feat[21:42) ----
    cudaEventRecord(evF, 0);
    cudaStreamWaitEvent(s1, evF, 0);
    ymap_kernel<21, 21><<<YG, 256, ymap_smem(21, 21), s1>>>(feat, CTOT, 0, Wf1, Wd1);
    cudaEventRecord(evJ, s1);
    knn_kernel<63><<<KNNG, 512, knn_smem(63)>>>(feat, CTOT, 0);
    cudaStreamWaitEvent(0, evJ, 0);
    pair_kernel<21, 12, 256><<<(TOTPT + 11) / 12, 256>>>(21);

    // ---- layer 2 : CIN=21, D=63, out=42 -> feat[42:84) ----
    cudaEventRecord(evF, 0);
    cudaStreamWaitEvent(s1, evF, 0);
    ymap_kernel<21, 42><<<YG, 256, ymap_smem(21, 42), s1>>>(feat, CTOT, 21, Wf2, Wd2);
    cudaEventRecord(evJ, s1);
    knn_kernel<63><<<KNNG, 512, knn_smem(63)>>>(feat, CTOT, 21);
    cudaStreamWaitEvent(0, evJ, 0);
    pair_kernel<42, 6, 256><<<(TOTPT + 5) / 6, 256>>>(42);

    // ---- layer 3 : CIN=42, D=126, out=85 -> feat[84:169) ----
    // side stream also computes final partial sums over c in [0,84)
    cudaEventRecord(evF, 0);
    cudaStreamWaitEvent(s1, evF, 0);
    ymap_kernel<42, 85><<<YG, 256, ymap_smem(42, 85), s1>>>(feat, CTOT, 42, Wf3, Wd3);
    final_part<<<BATCH * 31, 256, 0, s1>>>(Wf4, Wd4);
    cudaEventRecord(evJ, s1);
    knn_kernel<126><<<KNNG, 512, knn_smem(126)>>>(feat, CTOT, 42);
    cudaStreamWaitEvent(0, evJ, 0);
    pair_kernel<85, 3, 256><<<(TOTPT + 2) / 3, 256>>>(84);

    // ---- final VN layer remainder c in [84,169), leaky + mean over N ----
    final_rest<<<BATCH * 31, 256>>>(Wf4, Wd4, out);
}

// round 15
// speedup vs baseline: 1.1066x; 1.1066x over previous
#include <cuda_runtime.h>
#include <cfloat>

#define BATCH 8
#define NPT   1024
#define KNN   20
#define EPSV  1e-6f
#define CTOT  169
#define MAXCOUT 85
#define TOTPT (BATCH * NPT)
#define DSMEM 73728   // max(knn126: 73600, ymap42x85: 73248) rounded up

typedef unsigned long long u64;

// ---- packed f32x2 helpers (sm_10x FFMA2) ----
__device__ __forceinline__ u64 pk2(float lo, float hi) {
    u64 r; asm("mov.b64 %0,{%1,%2};" : "=l"(r) : "f"(lo), "f"(hi)); return r;
}
__device__ __forceinline__ void fma2(u64& d, u64 a, u64 b) {
    asm("fma.rn.f32x2 %0,%1,%2,%0;" : "+l"(d) : "l"(a), "l"(b));
}
__device__ __forceinline__ float2 up2(u64 v) {
    float2 r; asm("mov.b64 {%0,%1},%2;" : "=f"(r.x), "=f"(r.y) : "l"(v)); return r;
}
__device__ __forceinline__ unsigned ford(float v) {
    unsigned u = __float_as_uint(v);
    return (u & 0x80000000u) ? ~u : (u | 0x80000000u);
}

// -------- scratch --------
__device__ float  g_feat[BATCH * CTOT * 3 * NPT];
__device__ int    g_idx[BATCH * NPT * KNN];
__device__ float4 g_ypA[TOTPT * MAXCOUT];
__device__ float2 g_ypB[TOTPT * MAXCOUT];
__device__ float2 g_cmb[BATCH * NPT * MAXCOUT * 3];
__device__ float  g_pd [BATCH * 342 * 3 * NPT];

// -------- grid-wide barrier (all blocks resident by construction) --------
__device__ unsigned g_bar_cnt = 0;
__device__ unsigned g_bar_gen = 0;

__device__ __forceinline__ void grid_sync(int nblocks)
{
    __syncthreads();
    if (threadIdx.x == 0) {
        __threadfence();
        unsigned gen = *(volatile unsigned*)&g_bar_gen;
        unsigned a = atomicAdd(&g_bar_cnt, 1u);
        if (a == (unsigned)nblocks - 1u) {
            g_bar_cnt = 0;
            __threadfence();
            atomicAdd(&g_bar_gen, 1u);
        } else {
            unsigned cur;
            do { __nanosleep(128); cur = *(volatile unsigned*)&g_bar_gen; } while (cur == gen);
        }
        __threadfence();
    }
    __syncthreads();
}

// ================= knn tile (R10 body; tile in [0, 512)) =================
template <int D>
__device__ void knn_tile(const float* __restrict__ cur, int Ctot, int coff,
                         int tile, float* smraw)
{
    const int TI = 16;
    float (*sdist)[NPT] = (float(*)[NPT])smraw;
    u64   (*sxp)[8]     = (u64(*)[8])(smraw + TI * NPT);

    int b  = tile / (NPT / TI);
    int i0 = (tile % (NPT / TI)) * TI;
    int tid = threadIdx.x;
    const float* base = cur + (size_t)(b * Ctot + coff) * 3 * NPT;

    for (int f = tid; f < D; f += 256) {
        #pragma unroll
        for (int rp = 0; rp < 8; rp++) {
            float qa = base[f * NPT + i0 + 2 * rp];
            float qb = base[f * NPT + i0 + 2 * rp + 1];
            sxp[f][rp] = pk2(qa, qb);
        }
    }
    __syncthreads();

    {
        int j0 = tid * 4;
        const float* bp = base + j0;
        u64 acc[8][4];
        float xx[4] = {0.f, 0.f, 0.f, 0.f};
        #pragma unroll
        for (int rp = 0; rp < 8; rp++)
            #pragma unroll
            for (int jj = 0; jj < 4; jj++) acc[rp][jj] = 0ull;

        float4 xv0 = *(const float4*)bp;
        float4 xv1 = *(const float4*)(bp + (D > 1 ? NPT : 0));

        #pragma unroll 2
        for (int f = 0; f < D; f++) {
            int fn = f + 2 < D ? f + 2 : D - 1;
            float4 nxt = *(const float4*)(bp + (size_t)fn * NPT);

            float4 xv = xv0;
            u64 xp0 = pk2(xv.x, xv.x), xp1 = pk2(xv.y, xv.y);
            u64 xp2 = pk2(xv.z, xv.z), xp3 = pk2(xv.w, xv.w);
            u64 q[8];
            #pragma unroll
            for (int rp = 0; rp < 8; rp++) q[rp] = sxp[f][rp];
            #pragma unroll
            for (int rp = 0; rp < 8; rp++) {
                fma2(acc[rp][0], q[rp], xp0);
                fma2(acc[rp][1], q[rp], xp1);
                fma2(acc[rp][2], q[rp], xp2);
                fma2(acc[rp][3], q[rp], xp3);
            }
            xx[0] = fmaf(xv.x, xv.x, xx[0]);
            xx[1] = fmaf(xv.y, xv.y, xx[1]);
            xx[2] = fmaf(xv.z, xv.z, xx[2]);
            xx[3] = fmaf(xv.w, xv.w, xx[3]);

            xv0 = xv1; xv1 = nxt;
        }
        #pragma unroll
        for (int rp = 0; rp < 8; rp++) {
            float4 lo, hi;
            float2 v0 = up2(acc[rp][0]), v1 = up2(acc[rp][1]);
            float2 v2 = up2(acc[rp][2]), v3 = up2(acc[rp][3]);
            lo.x = 2.f * v0.x - xx[0]; hi.x = 2.f * v0.y - xx[0];
            lo.y = 2.f * v1.x - xx[1]; hi.y = 2.f * v1.y - xx[1];
            lo.z = 2.f * v2.x - xx[2]; hi.z = 2.f * v2.y - xx[2];
            lo.w = 2.f * v3.x - xx[3]; hi.w = 2.f * v3.y - xx[3];
            *(float4*)&sdist[2 * rp][j0]     = lo;
            *(float4*)&sdist[2 * rp + 1][j0] = hi;
        }
    }
    __syncthreads();

    int w = tid >> 5, lane = tid & 31;
    float* row0 = sdist[2 * w];
    float* row1 = sdist[2 * w + 1];
    int ob0 = (b * NPT + i0 + 2 * w) * KNN;
    int ob1 = ob0 + KNN;

    unsigned ck0, ck1; int ci0, ci1;
    {
        float lb0 = -FLT_MAX, lb1 = -FLT_MAX;
        int li0 = 0x7fffffff, li1 = 0x7fffffff;
        #pragma unroll 8
        for (int t = 0; t < 32; t++) {
            float v0 = row0[lane + 32 * t];
            float v1 = row1[lane + 32 * t];
            if (v0 > lb0) { lb0 = v0; li0 = lane + 32 * t; }
            if (v1 > lb1) { lb1 = v1; li1 = lane + 32 * t; }
        }
        ck0 = ford(lb0); ci0 = li0;
        ck1 = ford(lb1); ci1 = li1;
    }
    for (int it = 0; it < KNN; it++) {
        unsigned mx0 = __reduce_max_sync(0xffffffffu, ck0);
        unsigned mx1 = __reduce_max_sync(0xffffffffu, ck1);
        int wb0 = __reduce_min_sync(0xffffffffu, (ck0 == mx0) ? ci0 : 0x7fffffff);
        int wb1 = __reduce_min_sync(0xffffffffu, (ck1 == mx1) ? ci1 : 0x7fffffff);
        if (lane == 0) { g_idx[ob0 + it] = wb0; g_idx[ob1 + it] = wb1; }
        int own0 = wb0 & 31, own1 = wb1 & 31;
        if (lane == (wb0 >> 5)) row0[wb0] = -FLT_MAX;
        if (lane == (wb1 >> 5)) row1[wb1] = -FLT_MAX;
        float v0 = row0[own0 + 32 * lane];
        float v1 = row1[own1 + 32 * lane];
        unsigned k0 = ford(v0), k1 = ford(v1);
        unsigned m0 = __reduce_max_sync(0xffffffffu, k0);
        unsigned m1 = __reduce_max_sync(0xffffffffu, k1);
        int r0 = __reduce_min_sync(0xffffffffu, (k0 == m0) ? (own0 + 32 * lane) : 0x7fffffff);
        int r1 = __reduce_min_sync(0xffffffffu, (k1 == m1) ? (own1 + 32 * lane) : 0x7fffffff);
        if (lane == own0) { ck0 = m0; ci0 = r0; }
        if (lane == own1) { ck1 = m1; ci1 = r1; }
    }
    __syncthreads();   // smem reuse safety before next tile
}

// ================= ymap tile (R10 body; tile in [0, 256)) =================
template <int CIN, int COUT>
__device__ void ymap_tile(const float* __restrict__ cur, int Ctot, int coff,
                          const float* __restrict__ Wf, const float* __restrict__ Wd,
                          int tile, float* sm)
{
    const int IN2 = 2 * CIN;
    float4* sW = (float4*)sm;
    float*  sx = sm + 4 * CIN * COUT;

    int tid = threadIdx.x;
    int nn = tid & 31, og = tid >> 5;
    int pt0 = tile * 32;
    int b = pt0 >> 10, n0 = pt0 & (NPT - 1);
    const float* base = cur + (size_t)(b * Ctot + coff) * 3 * NPT;

    for (int t = tid; t < CIN * COUT; t += 256) {
        int c = t / COUT, o = t - c * COUT;
        sW[t] = make_float4(Wf[o * IN2 + c], Wd[o * IN2 + c],
                            Wf[o * IN2 + CIN + c], Wd[o * IN2 + CIN + c]);
    }
    for (int t = tid; t < 3 * CIN * 32; t += 256) {
        int row = t >> 5, col = t & 31;
        sx[t] = base[row * NPT + n0 + col];
    }
    __syncthreads();

    int pt = pt0 + nn;
    for (int o = og; o < COUT; o += 8) {
        u64 accL0 = 0ull, accL1 = 0ull, accL2 = 0ull;
        u64 accR0 = 0ull, accR1 = 0ull, accR2 = 0ull;
        for (int c = 0; c < CIN; c++) {
            float4 w = sW[c * COUT + o];
            u64 wl = pk2(w.x, w.y);
            u64 wr = pk2(w.z, w.w);
            float x0 = sx[(c * 3 + 0) * 32 + nn];
            float x1 = sx[(c * 3 + 1) * 32 + nn];
            float x2 = sx[(c * 3 + 2) * 32 + nn];
            u64 p0 = pk2(x0, x0), p1 = pk2(x1, x1), p2 = pk2(x2, x2);
            fma2(accL0, wl, p0); fma2(accR0, wr, p0);
            fma2(accL1, wl, p1); fma2(accR1, wr, p1);
            fma2(accL2, wl, p2); fma2(accR2, wr, p2);
        }
        float2 l0 = up2(accL0), l1 = up2(accL1), l2 = up2(accL2);
        float2 r0 = up2(accR0), r1 = up2(accR1), r2 = up2(accR2);
        g_ypA[(size_t)pt * COUT + o] = make_float4(l0.x, l0.y, l1.x, l1.y);
        g_ypB[(size_t)pt * COUT + o] = make_float2(l2.x, l2.y);
        float2* co = g_cmb + ((size_t)pt * COUT + o) * 3;
        co[0] = make_float2(r0.x - l0.x, r0.y - l0.y);
        co[1] = make_float2(r1.x - l1.x, r1.y - l1.y);
        co[2] = make_float2(r2.x - l2.x, r2.y - l2.y);
    }
    __syncthreads();
}

// ================= pair tile (R10 body) =================
template <int COUT, int P>
__device__ void pair_tile(int ooff, int tile)
{
    __shared__ int sidx[P][KNN];
    int tid = threadIdx.x;
    int pt0 = tile * P;

    for (int t = tid; t < P * KNN; t += 256) {
        int p = t / KNN;
        if (pt0 + p < TOTPT) sidx[p][t - p * KNN] = g_idx[(pt0 + p) * KNN + (t - p * KNN)];
    }
    __syncthreads();

    int ln = tid / COUT, o = tid - ln * COUT;
    int pt = pt0 + ln;
    if (ln < P && pt < TOTPT) {
        int b = pt >> 10, n = pt & (NPT - 1);

        const float2* cmb = g_cmb + ((size_t)pt * COUT + o) * 3;
        float2 c0 = cmb[0], c1 = cmb[1], c2 = cmb[2];

        float a0 = 0.f, a1 = 0.f, a2 = 0.f;
        #pragma unroll 5
        for (int j = 0; j < KNN; j++) {
            int nj = sidx[ln][j];
            size_t yi = ((size_t)(b << 10) + nj) * COUT + o;
            float4 A  = g_ypA[yi];
            float2 Bv = g_ypB[yi];
            float P0 = A.x  + c0.x, D0 = A.y  + c0.y;
            float P1 = A.z  + c1.x, D1 = A.w  + c1.y;
            float P2 = Bv.x + c2.x, D2 = Bv.y + c2.y;
            float dot = P0 * D0 + P1 * D1 + P2 * D2;
            float dsq = D0 * D0 + D1 * D1 + D2 * D2;
            float s = dot / (dsq + EPSV);
            float s0, s1, s2;
            if (dot >= 0.f) { s0 = P0; s1 = P1; s2 = P2; }
            else { s0 = P0 - s * D0; s1 = P1 - s * D1; s2 = P2 - s * D2; }
            a0 += 0.2f * P0 + 0.8f * s0;
            a1 += 0.2f * P1 + 0.8f * s1;
            a2 += 0.2f * P2 + 0.8f * s2;
        }
        const float invK = 1.f / KNN;
        float* fo = g_feat + (((size_t)b * CTOT + ooff + o) * 3) * NPT + n;
        fo[0 * NPT] = a0 * invK;
        fo[1 * NPT] = a1 * invK;
        fo[2 * NPT] = a2 * invK;
    }
    __syncthreads();
}

// ========== final part 1: partial sums over c in [0,84); tile in [0,248) ==========
__device__ void final_part_tile(const float* __restrict__ Wf, const float* __restrict__ Wd,
                                int tile)
{
    const int OT = 11, CI = CTOT, CP = 84;
    __shared__ u64 sWfp[OT * CP];
    __shared__ u64 sWdp[CP];
    int b  = tile / 31;
    int o0 = (tile % 31) * OT;
    int tid = threadIdx.x;

    for (int t = tid; t < OT * CP; t += 256) {
        int o = t / CP, c = t - o * CP;
        float w = Wf[(o0 + o) * CI + c];
        sWfp[t] = pk2(w, w);
    }
    for (int t = tid; t < CP; t += 256) { float w = Wd[t]; sWdp[t] = pk2(w, w); }
    __syncthreads();

    const float* fb = g_feat + (size_t)b * CTOT * 3 * NPT;
    float* pb = g_pd + (size_t)b * 342 * 3 * NPT;
    for (int it = 0; it < 2; it++) {
        int n = 2 * (tid + it * 256);
        u64 p0[OT], p1[OT], p2[OT];
        u64 d0 = 0ull, d1 = 0ull, d2 = 0ull;
        #pragma unroll
        for (int o = 0; o < OT; o++) { p0[o] = p1[o] = p2[o] = 0ull; }

        for (int c = 0; c < CP; c++) {
            u64 x0 = *(const u64*)(fb + (c * 3 + 0) * NPT + n);
            u64 x1 = *(const u64*)(fb + (c * 3 + 1) * NPT + n);
            u64 x2 = *(const u64*)(fb + (c * 3 + 2) * NPT + n);
            u64 wd = sWdp[c];
            fma2(d0, wd, x0); fma2(d1, wd, x1); fma2(d2, wd, x2);
            #pragma unroll
            for (int o = 0; o < OT; o++) {
                u64 wf = sWfp[o * CP + c];
                fma2(p0[o], wf, x0); fma2(p1[o], wf, x1); fma2(p2[o], wf, x2);
            }
        }
        #pragma unroll
        for (int o = 0; o < OT; o++) {
            *(u64*)&pb[((o0 + o) * 3 + 0) * NPT + n] = p0[o];
            *(u64*)&pb[((o0 + o) * 3 + 1) * NPT + n] = p1[o];
            *(u64*)&pb[((o0 + o) * 3 + 2) * NPT + n] = p2[o];
        }
        if (o0 == 0) {
            *(u64*)&pb[(341 * 3 + 0) * NPT + n] = d0;
            *(u64*)&pb[(341 * 3 + 1) * NPT + n] = d1;
            *(u64*)&pb[(341 * 3 + 2) * NPT + n] = d2;
        }
    }
    __syncthreads();
}

// ========== final part 2: c in [84,169), leaky + mean over N; tile in [0,248) ==========
__device__ void final_rest_tile(const float* __restrict__ Wf, const float* __restrict__ Wd,
                                float* __restrict__ out, int tile)
{
    const int OT = 11, CI = CTOT, CP = 84, CR = CI - CP;
    __shared__ u64   sWfp[OT * CR];
    __shared__ u64   sWdp[CR];
    __shared__ float sacc[OT * 3];
    int b  = tile / 31;
    int o0 = (tile % 31) * OT;
    int tid = threadIdx.x;

    for (int t = tid; t < OT * CR; t += 256) {
        int o = t / CR, c = t - o * CR;
        float w = Wf[(o0 + o) * CI + CP + c];
        sWfp[t] = pk2(w, w);
    }
    for (int t = tid; t < CR; t += 256) { float w = Wd[CP + t]; sWdp[t] = pk2(w, w); }
    if (tid < OT * 3) sacc[tid] = 0.f;
    __syncthreads();

    float sum[OT][3];
    #pragma unroll
    for (int o = 0; o < OT; o++) { sum[o][0] = sum[o][1] = sum[o][2] = 0.f; }

    const float* fb = g_feat + (size_t)b * CTOT * 3 * NPT;
    const float* pb = g_pd + (size_t)b * 342 * 3 * NPT;
    for (int it = 0; it < 2; it++) {
        int n = 2 * (tid + it * 256);
        u64 p0[OT], p1[OT], p2[OT];
        #pragma unroll
        for (int o = 0; o < OT; o++) {
            p0[o] = *(const u64*)&pb[((o0 + o) * 3 + 0) * NPT + n];
            p1[o] = *(const u64*)&pb[((o0 + o) * 3 + 1) * NPT + n];
            p2[o] = *(const u64*)&pb[((o0 + o) * 3 + 2) * NPT + n];
        }
        u64 d0 = *(const u64*)&pb[(341 * 3 + 0) * NPT + n];
        u64 d1 = *(const u64*)&pb[(341 * 3 + 1) * NPT + n];
        u64 d2 = *(const u64*)&pb[(341 * 3 + 2) * NPT + n];

        for (int c = 0; c < CR; c++) {
            u64 x0 = *(const u64*)(fb + ((CP + c) * 3 + 0) * NPT + n);
            u64 x1 = *(const u64*)(fb + ((CP + c) * 3 + 1) * NPT + n);
            u64 x2 = *(const u64*)(fb + ((CP + c) * 3 + 2) * NPT + n);
            u64 wd = sWdp[c];
            fma2(d0, wd, x0); fma2(d1, wd, x1); fma2(d2, wd, x2);
            #pragma unroll
            for (int o = 0; o < OT; o++) {
                u64 wf = sWfp[o * CR + c];
                fma2(p0[o], wf, x0); fma2(p1[o], wf, x1); fma2(p2[o], wf, x2);
            }
        }
        float2 D0 = up2(d0), D1 = up2(d1), D2 = up2(d2);
        float invA = 1.f / (D0.x * D0.x + D1.x * D1.x + D2.x * D2.x + EPSV);
        float invB = 1.f / (D0.y * D0.y + D1.y * D1.y + D2.y * D2.y + EPSV);
        #pragma unroll
        for (int o = 0; o < OT; o++) {
            float2 P0 = up2(p0[o]), P1 = up2(p1[o]), P2 = up2(p2[o]);
            {
                float dot = P0.x * D0.x + P1.x * D1.x + P2.x * D2.x;
                float s0, s1, s2;
                if (dot >= 0.f) { s0 = P0.x; s1 = P1.x; s2 = P2.x; }
                else {
                    float sc = dot * invA;
                    s0 = P0.x - sc * D0.x; s1 = P1.x - sc * D1.x; s2 = P2.x - sc * D2.x;
                }
                sum[o][0] += 0.2f * P0.x + 0.8f * s0;
                sum[o][1] += 0.2f * P1.x + 0.8f * s1;
                sum[o][2] += 0.2f * P2.x + 0.8f * s2;
            }
            {
                float dot = P0.y * D0.y + P1.y * D1.y + P2.y * D2.y;
                float s0, s1, s2;
                if (dot >= 0.f) { s0 = P0.y; s1 = P1.y; s2 = P2.y; }
                else {
                    float sc = dot * invB;
                    s0 = P0.y - sc * D0.y; s1 = P1.y - sc * D1.y; s2 = P2.y - sc * D2.y;
                }
                sum[o][0] += 0.2f * P0.y + 0.8f * s0;
                sum[o][1] += 0.2f * P1.y + 0.8f * s1;
                sum[o][2] += 0.2f * P2.y + 0.8f * s2;
            }
        }
    }
    #pragma unroll
    for (int o = 0; o < OT; o++)
        #pragma unroll
        for (int dd = 0; dd < 3; dd++) {
            float v = sum[o][dd];
            #pragma unroll
            for (int s = 16; s; s >>= 1) v += __shfl_down_sync(0xffffffffu, v, s);
            if ((tid & 31) == 0) atomicAdd(&sacc[o * 3 + dd], v);
        }
    __syncthreads();
    if (tid < OT * 3) out[b * 1023 + o0 * 3 + tid] = sacc[tid] * (1.f / NPT);
    __syncthreads();
}

// ================= mega kernel: whole network, one launch =================
#define KT 512            // knn tiles per layer (8 batches * 64)
#define YT 256            // ymap tiles per layer
#define FT 248            // final tiles

__global__ __launch_bounds__(256, 2)
void vn_mega(const float* __restrict__ x,
             const float* __restrict__ Wf0, const float* __restrict__ Wd0,
             const float* __restrict__ Wf1, const float* __restrict__ Wd1,
             const float* __restrict__ Wf2, const float* __restrict__ Wd2,
             const float* __restrict__ Wf3, const float* __restrict__ Wd3,
             const float* __restrict__ Wf4, const float* __restrict__ Wd4,
             float* __restrict__ out)
{
    extern __shared__ float smraw[];
    const float* feat = g_feat;
    int nb = gridDim.x;

    // ---- layer 0 ----
    for (int it = blockIdx.x; it < KT + YT; it += nb) {
        if (it < KT) knn_tile<3>(x, 1, 0, it, smraw);
        else         ymap_tile<1, 21>(x, 1, 0, Wf0, Wd0, it - KT, smraw);
    }
    grid_sync(nb);
    for (int it = blockIdx.x; it < (TOTPT + 11) / 12; it += nb) pair_tile<21, 12>(0, it);
    grid_sync(nb);

    // ---- layer 1 ----
    for (int it = blockIdx.x; it < KT + YT; it += nb) {
        if (it < KT) knn_tile<63>(feat, CTOT, 0, it, smraw);
        else         ymap_tile<21, 21>(feat, CTOT, 0, Wf1, Wd1, it - KT, smraw);
    }
    grid_sync(nb);
    for (int it = blockIdx.x; it < (TOTPT + 11) / 12; it += nb) pair_tile<21, 12>(21, it);
    grid_sync(nb);

    // ---- layer 2 ----
    for (int it = blockIdx.x; it < KT + YT; it += nb) {
        if (it < KT) knn_tile<63>(feat, CTOT, 21, it, smraw);
        else         ymap_tile<21, 42>(feat, CTOT, 21, Wf2, Wd2, it - KT, smraw);
    }
    grid_sync(nb);
    for (int it = blockIdx.x; it < (TOTPT + 5) / 6; it += nb) pair_tile<42, 6>(42, it);
    grid_sync(nb);

    // ---- layer 3 (+ final partial sums over completed feat[0:84)) ----
    for (int it = blockIdx.x; it < KT + YT + FT; it += nb) {
        if (it < KT)           knn_tile<126>(feat, CTOT, 42, it, smraw);
        else if (it < KT + YT) ymap_tile<42, 85>(feat, CTOT, 42, Wf3, Wd3, it - KT, smraw);
        else                   final_part_tile(Wf4, Wd4, it - KT - YT);
    }
    grid_sync(nb);
    for (int it = blockIdx.x; it < (TOTPT + 2) / 3; it += nb) pair_tile<85, 3>(84, it);
    grid_sync(nb);

    // ---- final remainder + mean over N ----
    for (int it = blockIdx.x; it < FT; it += nb) final_rest_tile(Wf4, Wd4, out, it);
}

// ================= launch =================
extern "C" void kernel_launch(void* const* d_in, const int* in_sizes, int n_in,
                              void* d_out, int out_size)
{
    const float* x   = (const float*)d_in[0];
    const float* Wf0 = (const float*)d_in[1];
    const float* Wd0 = (const float*)d_in[2];
    const float* Wf1 = (const float*)d_in[3];
    const float* Wd1 = (const float*)d_in[4];
    const float* Wf2 = (const float*)d_in[5];
    const float* Wd2 = (const float*)d_in[6];
    const float* Wf3 = (const float*)d_in[7];
    const float* Wd3 = (const float*)d_in[8];
    const float* Wf4 = (const float*)d_in[9];
    const float* Wd4 = (const float*)d_in[10];
    float* out = (float*)d_out;

    static int nblocks = 0;
    static bool init_done = false;
    if (!init_done) {
        int sms = 0;
        cudaDeviceGetAttribute(&sms, cudaDevAttrMultiProcessorCount, 0);
        if (sms <= 0) sms = 148;
        nblocks = 2 * sms;
        cudaFuncSetAttribute(vn_mega, cudaFuncAttributeMaxDynamicSharedMemorySize, DSMEM);
        init_done = true;
    }

    vn_mega<<<nblocks, 256, DSMEM>>>(x, Wf0, Wd0, Wf1, Wd1, Wf2, Wd2,
                                     Wf3, Wd3, Wf4, Wd4, out);
}

// round 17
// speedup vs baseline: 1.1592x; 1.0475x over previous
#include <cuda_runtime.h>
#include <cfloat>

#define BATCH 8
#define NPT   1024
#define KNN   20
#define EPSV  1e-6f
#define CTOT  169
#define MAXCOUT 85
#define TOTPT (BATCH * NPT)
#define DSMEM 73728

typedef unsigned long long u64;

// XOR swizzle at float4 granularity: sequential scan stays conflict-free,
// strided rescan (stride 32 floats) drops from 32-way to 4-way conflicts,
// float4 stores stay 16B-aligned.
#define SWZ(j) ((j) ^ ((((j) >> 7) & 7) << 2))

// ---- packed f32x2 helpers (sm_10x FFMA2) ----
__device__ __forceinline__ u64 pk2(float lo, float hi) {
    u64 r; asm("mov.b64 %0,{%1,%2};" : "=l"(r) : "f"(lo), "f"(hi)); return r;
}
__device__ __forceinline__ void fma2(u64& d, u64 a, u64 b) {
    asm("fma.rn.f32x2 %0,%1,%2,%0;" : "+l"(d) : "l"(a), "l"(b));
}
__device__ __forceinline__ float2 up2(u64 v) {
    float2 r; asm("mov.b64 {%0,%1},%2;" : "=f"(r.x), "=f"(r.y) : "l"(v)); return r;
}
__device__ __forceinline__ unsigned ford(float v) {
    unsigned u = __float_as_uint(v);
    return (u & 0x80000000u) ? ~u : (u | 0x80000000u);
}

// -------- scratch --------
__device__ float  g_feat[BATCH * CTOT * 3 * NPT];
__device__ int    g_idx[BATCH * NPT * KNN];
__device__ float4 g_ypA[TOTPT * MAXCOUT];
__device__ float2 g_ypB[TOTPT * MAXCOUT];
__device__ float2 g_cmb[BATCH * NPT * MAXCOUT * 3];
__device__ float  g_pd [BATCH * 342 * 3 * NPT];

// -------- grid barrier + per-phase dynamic work tickets --------
__device__ unsigned g_bar_cnt = 0;
__device__ unsigned g_bar_gen = 0;
__device__ unsigned g_ticket[12];   // zero-init; reset at kernel end

__device__ __forceinline__ void grid_sync(int nblocks)
{
    __syncthreads();
    if (threadIdx.x == 0) {
        __threadfence();
        unsigned gen = *(volatile unsigned*)&g_bar_gen;
        unsigned a = atomicAdd(&g_bar_cnt, 1u);
        if (a == (unsigned)nblocks - 1u) {
            g_bar_cnt = 0;
            __threadfence();
            atomicAdd(&g_bar_gen, 1u);
        } else {
            unsigned cur;
            do { __nanosleep(128); cur = *(volatile unsigned*)&g_bar_gen; } while (cur == gen);
        }
        __threadfence();
    }
    __syncthreads();
}

// dynamic ticket: tid0 pulls a tile id, broadcast via shared. Caller's tile
// bodies all end in __syncthreads(), which orders reuse of s_it.
__device__ __forceinline__ int next_tile(int ph, int* s_it)
{
    if (threadIdx.x == 0) *s_it = (int)atomicAdd(&g_ticket[ph], 1u);
    __syncthreads();
    return *s_it;
}

// ================= knn tile (swizzled sdist) =================
template <int D>
__device__ void knn_tile(const float* __restrict__ cur, int Ctot, int coff,
                         int tile, float* smraw)
{
    const int TI = 16;
    float (*sdist)[NPT] = (float(*)[NPT])smraw;
    u64   (*sxp)[8]     = (u64(*)[8])(smraw + TI * NPT);

    int b  = tile / (NPT / TI);
    int i0 = (tile % (NPT / TI)) * TI;
    int tid = threadIdx.x;
    const float* base = cur + (size_t)(b * Ctot + coff) * 3 * NPT;

    for (int f = tid; f < D; f += 256) {
        #pragma unroll
        for (int rp = 0; rp < 8; rp++) {
            float qa = base[f * NPT + i0 + 2 * rp];
            float qb = base[f * NPT + i0 + 2 * rp + 1];
            sxp[f][rp] = pk2(qa, qb);
        }
    }
    __syncthreads();

    {
        int j0 = tid * 4;
        int j0s = SWZ(j0);
        const float* bp = base + j0;
        u64 acc[8][4];
        float xx[4] = {0.f, 0.f, 0.f, 0.f};
        #pragma unroll
        for (int rp = 0; rp < 8; rp++)
            #pragma unroll
            for (int jj = 0; jj < 4; jj++) acc[rp][jj] = 0ull;

        float4 xv0 = *(const float4*)bp;
        float4 xv1 = *(const float4*)(bp + (D > 1 ? NPT : 0));

        #pragma unroll 2
        for (int f = 0; f < D; f++) {
            int fn = f + 2 < D ? f + 2 : D - 1;
            float4 nxt = *(const float4*)(bp + (size_t)fn * NPT);

            float4 xv = xv0;
            u64 xp0 = pk2(xv.x, xv.x), xp1 = pk2(xv.y, xv.y);
            u64 xp2 = pk2(xv.z, xv.z), xp3 = pk2(xv.w, xv.w);
            u64 q[8];
            #pragma unroll
            for (int rp = 0; rp < 8; rp++) q[rp] = sxp[f][rp];
            #pragma unroll
            for (int rp = 0; rp < 8; rp++) {
                fma2(acc[rp][0], q[rp], xp0);
                fma2(acc[rp][1], q[rp], xp1);
                fma2(acc[rp][2], q[rp], xp2);
                fma2(acc[rp][3], q[rp], xp3);
            }
            xx[0] = fmaf(xv.x, xv.x, xx[0]);
            xx[1] = fmaf(xv.y, xv.y, xx[1]);
            xx[2] = fmaf(xv.z, xv.z, xx[2]);
            xx[3] = fmaf(xv.w, xv.w, xx[3]);

            xv0 = xv1; xv1 = nxt;
        }
        #pragma unroll
        for (int rp = 0; rp < 8; rp++) {
            float4 lo, hi;
            float2 v0 = up2(acc[rp][0]), v1 = up2(acc[rp][1]);
            float2 v2 = up2(acc[rp][2]), v3 = up2(acc[rp][3]);
            lo.x = 2.f * v0.x - xx[0]; hi.x = 2.f * v0.y - xx[0];
            lo.y = 2.f * v1.x - xx[1]; hi.y = 2.f * v1.y - xx[1];
            lo.z = 2.f * v2.x - xx[2]; hi.z = 2.f * v2.y - xx[2];
            lo.w = 2.f * v3.x - xx[3]; hi.w = 2.f * v3.y - xx[3];
            *(float4*)&sdist[2 * rp][j0s]     = lo;
            *(float4*)&sdist[2 * rp + 1][j0s] = hi;
        }
    }
    __syncthreads();

    int w = tid >> 5, lane = tid & 31;
    float* row0 = sdist[2 * w];
    float* row1 = sdist[2 * w + 1];
    int ob0 = (b * NPT + i0 + 2 * w) * KNN;
    int ob1 = ob0 + KNN;

    unsigned ck0, ck1; int ci0, ci1;
    {
        float lb0 = -FLT_MAX, lb1 = -FLT_MAX;
        int li0 = 0x7fffffff, li1 = 0x7fffffff;
        #pragma unroll 8
        for (int t = 0; t < 32; t++) {
            int j = lane + 32 * t, js = SWZ(j);
            float v0 = row0[js];
            float v1 = row1[js];
            if (v0 > lb0) { lb0 = v0; li0 = j; }
            if (v1 > lb1) { lb1 = v1; li1 = j; }
        }
        ck0 = ford(lb0); ci0 = li0;
        ck1 = ford(lb1); ci1 = li1;
    }
    for (int it = 0; it < KNN; it++) {
        unsigned mx0 = __reduce_max_sync(0xffffffffu, ck0);
        unsigned mx1 = __reduce_max_sync(0xffffffffu, ck1);
        int wb0 = __reduce_min_sync(0xffffffffu, (ck0 == mx0) ? ci0 : 0x7fffffff);
        int wb1 = __reduce_min_sync(0xffffffffu, (ck1 == mx1) ? ci1 : 0x7fffffff);
        if (lane == 0) { g_idx[ob0 + it] = wb0; g_idx[ob1 + it] = wb1; }
        int own0 = wb0 & 31, own1 = wb1 & 31;
        if (lane == (wb0 >> 5)) row0[SWZ(wb0)] = -FLT_MAX;
        if (lane == (wb1 >> 5)) row1[SWZ(wb1)] = -FLT_MAX;
        int jr0 = own0 + 32 * lane, jr1 = own1 + 32 * lane;
        float v0 = row0[SWZ(jr0)];
        float v1 = row1[SWZ(jr1)];
        unsigned k0 = ford(v0), k1 = ford(v1);
        unsigned m0 = __reduce_max_sync(0xffffffffu, k0);
        unsigned m1 = __reduce_max_sync(0xffffffffu, k1);
        int r0 = __reduce_min_sync(0xffffffffu, (k0 == m0) ? jr0 : 0x7fffffff);
        int r1 = __reduce_min_sync(0xffffffffu, (k1 == m1) ? jr1 : 0x7fffffff);
        if (lane == own0) { ck0 = m0; ci0 = r0; }
        if (lane == own1) { ck1 = m1; ci1 = r1; }
    }
    __syncthreads();
}

// ================= ymap tile =================
template <int CIN, int COUT>
__device__ void ymap_tile(const float* __restrict__ cur, int Ctot, int coff,
                          const float* __restrict__ Wf, const float* __restrict__ Wd,
                          int tile, float* sm)
{
    const int IN2 = 2 * CIN;
    float4* sW = (float4*)sm;
    float*  sx = sm + 4 * CIN * COUT;

    int tid = threadIdx.x;
    int nn = tid & 31, og = tid >> 5;
    int pt0 = tile * 32;
    int b = pt0 >> 10, n0 = pt0 & (NPT - 1);
    const float* base = cur + (size_t)(b * Ctot + coff) * 3 * NPT;

    for (int t = tid; t < CIN * COUT; t += 256) {
        int c = t / COUT, o = t - c * COUT;
        sW[t] = make_float4(Wf[o * IN2 + c], Wd[o * IN2 + c],
                            Wf[o * IN2 + CIN + c], Wd[o * IN2 + CIN + c]);
    }
    for (int t = tid; t < 3 * CIN * 32; t += 256) {
        int row = t >> 5, col = t & 31;
        sx[t] = base[row * NPT + n0 + col];
    }
    __syncthreads();

    int pt = pt0 + nn;
    for (int o = og; o < COUT; o += 8) {
        u64 accL0 = 0ull, accL1 = 0ull, accL2 = 0ull;
        u64 accR0 = 0ull, accR1 = 0ull, accR2 = 0ull;
        for (int c = 0; c < CIN; c++) {
            float4 w = sW[c * COUT + o];
            u64 wl = pk2(w.x, w.y);
            u64 wr = pk2(w.z, w.w);
            float x0 = sx[(c * 3 + 0) * 32 + nn];
            float x1 = sx[(c * 3 + 1) * 32 + nn];
            float x2 = sx[(c * 3 + 2) * 32 + nn];
            u64 p0 = pk2(x0, x0), p1 = pk2(x1, x1), p2 = pk2(x2, x2);
            fma2(accL0, wl, p0); fma2(accR0, wr, p0);
            fma2(accL1, wl, p1); fma2(accR1, wr, p1);
            fma2(accL2, wl, p2); fma2(accR2, wr, p2);
        }
        float2 l0 = up2(accL0), l1 = up2(accL1), l2 = up2(accL2);
        float2 r0 = up2(accR0), r1 = up2(accR1), r2 = up2(accR2);
        g_ypA[(size_t)pt * COUT + o] = make_float4(l0.x, l0.y, l1.x, l1.y);
        g_ypB[(size_t)pt * COUT + o] = make_float2(l2.x, l2.y);
        float2* co = g_cmb + ((size_t)pt * COUT + o) * 3;
        co[0] = make_float2(r0.x - l0.x, r0.y - l0.y);
        co[1] = make_float2(r1.x - l1.x, r1.y - l1.y);
        co[2] = make_float2(r2.x - l2.x, r2.y - l2.y);
    }
    __syncthreads();
}

// ================= pair tile =================
template <int COUT, int P>
__device__ void pair_tile(int ooff, int tile)
{
    __shared__ int sidx[P][KNN];
    int tid = threadIdx.x;
    int pt0 = tile * P;

    for (int t = tid; t < P * KNN; t += 256) {
        int p = t / KNN;
        if (pt0 + p < TOTPT) sidx[p][t - p * KNN] = g_idx[(pt0 + p) * KNN + (t - p * KNN)];
    }
    __syncthreads();

    int ln = tid / COUT, o = tid - ln * COUT;
    int pt = pt0 + ln;
    if (ln < P && pt < TOTPT) {
        int b = pt >> 10, n = pt & (NPT - 1);

        const float2* cmb = g_cmb + ((size_t)pt * COUT + o) * 3;
        float2 c0 = cmb[0], c1 = cmb[1], c2 = cmb[2];

        float a0 = 0.f, a1 = 0.f, a2 = 0.f;
        #pragma unroll 5
        for (int j = 0; j < KNN; j++) {
            int nj = sidx[ln][j];
            size_t yi = ((size_t)(b << 10) + nj) * COUT + o;
            float4 A  = g_ypA[yi];
            float2 Bv = g_ypB[yi];
            float P0 = A.x  + c0.x, D0 = A.y  + c0.y;
            float P1 = A.z  + c1.x, D1 = A.w  + c1.y;
            float P2 = Bv.x + c2.x, D2 = Bv.y + c2.y;
            float dot = P0 * D0 + P1 * D1 + P2 * D2;
            float dsq = D0 * D0 + D1 * D1 + D2 * D2;
            float s = dot / (dsq + EPSV);
            float s0, s1, s2;
            if (dot >= 0.f) { s0 = P0; s1 = P1; s2 = P2; }
            else { s0 = P0 - s * D0; s1 = P1 - s * D1; s2 = P2 - s * D2; }
            a0 += 0.2f * P0 + 0.8f * s0;
            a1 += 0.2f * P1 + 0.8f * s1;
            a2 += 0.2f * P2 + 0.8f * s2;
        }
        const float invK = 1.f / KNN;
        float* fo = g_feat + (((size_t)b * CTOT + ooff + o) * 3) * NPT + n;
        fo[0 * NPT] = a0 * invK;
        fo[1 * NPT] = a1 * invK;
        fo[2 * NPT] = a2 * invK;
    }
    __syncthreads();
}

// ========== final part 1 ==========
__device__ void final_part_tile(const float* __restrict__ Wf, const float* __restrict__ Wd,
                                int tile)
{
    const int OT = 11, CI = CTOT, CP = 84;
    __shared__ u64 sWfp[OT * CP];
    __shared__ u64 sWdp[CP];
    int b  = tile / 31;
    int o0 = (tile % 31) * OT;
    int tid = threadIdx.x;

    for (int t = tid; t < OT * CP; t += 256) {
        int o = t / CP, c = t - o * CP;
        float w = Wf[(o0 + o) * CI + c];
        sWfp[t] = pk2(w, w);
    }
    for (int t = tid; t < CP; t += 256) { float w = Wd[t]; sWdp[t] = pk2(w, w); }
    __syncthreads();

    const float* fb = g_feat + (size_t)b * CTOT * 3 * NPT;
    float* pb = g_pd + (size_t)b * 342 * 3 * NPT;
    for (int it = 0; it < 2; it++) {
        int n = 2 * (tid + it * 256);
        u64 p0[OT], p1[OT], p2[OT];
        u64 d0 = 0ull, d1 = 0ull, d2 = 0ull;
        #pragma unroll
        for (int o = 0; o < OT; o++) { p0[o] = p1[o] = p2[o] = 0ull; }

        for (int c = 0; c < CP; c++) {
            u64 x0 = *(const u64*)(fb + (c * 3 + 0) * NPT + n);
            u64 x1 = *(const u64*)(fb + (c * 3 + 1) * NPT + n);
            u64 x2 = *(const u64*)(fb + (c * 3 + 2) * NPT + n);
            u64 wd = sWdp[c];
            fma2(d0, wd, x0); fma2(d1, wd, x1); fma2(d2, wd, x2);
            #pragma unroll
            for (int o = 0; o < OT; o++) {
                u64 wf = sWfp[o * CP + c];
                fma2(p0[o], wf, x0); fma2(p1[o], wf, x1); fma2(p2[o], wf, x2);
            }
        }
        #pragma unroll
        for (int o = 0; o < OT; o++) {
            *(u64*)&pb[((o0 + o) * 3 + 0) * NPT + n] = p0[o];
            *(u64*)&pb[((o0 + o) * 3 + 1) * NPT + n] = p1[o];
            *(u64*)&pb[((o0 + o) * 3 + 2) * NPT + n] = p2[o];
        }
        if (o0 == 0) {
            *(u64*)&pb[(341 * 3 + 0) * NPT + n] = d0;
            *(u64*)&pb[(341 * 3 + 1) * NPT + n] = d1;
            *(u64*)&pb[(341 * 3 + 2) * NPT + n] = d2;
        }
    }
    __syncthreads();
}

// ========== final part 2 ==========
__device__ void final_rest_tile(const float* __restrict__ Wf, const float* __restrict__ Wd,
                                float* __restrict__ out, int tile)
{
    const int OT = 11, CI = CTOT, CP = 84, CR = CI - CP;
    __shared__ u64   sWfp[OT * CR];
    __shared__ u64   sWdp[CR];
    __shared__ float sacc[OT * 3];
    int b  = tile / 31;
    int o0 = (tile % 31) * OT;
    int tid = threadIdx.x;

    for (int t = tid; t < OT * CR; t += 256) {
        int o = t / CR, c = t - o * CR;
        float w = Wf[(o0 + o) * CI + CP + c];
        sWfp[t] = pk2(w, w);
    }
    for (int t = tid; t < CR; t += 256) { float w = Wd[CP + t]; sWdp[t] = pk2(w, w); }
    if (tid < OT * 3) sacc[tid] = 0.f;
    __syncthreads();

    float sum[OT][3];
    #pragma unroll
    for (int o = 0; o < OT; o++) { sum[o][0] = sum[o][1] = sum[o][2] = 0.f; }

    const float* fb = g_feat + (size_t)b * CTOT * 3 * NPT;
    const float* pb = g_pd + (size_t)b * 342 * 3 * NPT;
    for (int it = 0; it < 2; it++) {
        int n = 2 * (tid + it * 256);
        u64 p0[OT], p1[OT], p2[OT];
        #pragma unroll
        for (int o = 0; o < OT; o++) {
            p0[o] = *(const u64*)&pb[((o0 + o) * 3 + 0) * NPT + n];
            p1[o] = *(const u64*)&pb[((o0 + o) * 3 + 1) * NPT + n];
            p2[o] = *(const u64*)&pb[((o0 + o) * 3 + 2) * NPT + n];
        }
        u64 d0 = *(const u64*)&pb[(341 * 3 + 0) * NPT + n];
        u64 d1 = *(const u64*)&pb[(341 * 3 + 1) * NPT + n];
        u64 d2 = *(const u64*)&pb[(341 * 3 + 2) * NPT + n];

        for (int c = 0; c < CR; c++) {
            u64 x0 = *(const u64*)(fb + ((CP + c) * 3 + 0) * NPT + n);
            u64 x1 = *(const u64*)(fb + ((CP + c) * 3 + 1) * NPT + n);
            u64 x2 = *(const u64*)(fb + ((CP + c) * 3 + 2) * NPT + n);
            u64 wd = sWdp[c];
            fma2(d0, wd, x0); fma2(d1, wd, x1); fma2(d2, wd, x2);
            #pragma unroll
            for (int o = 0; o < OT; o++) {
                u64 wf = sWfp[o * CR + c];
                fma2(p0[o], wf, x0); fma2(p1[o], wf, x1); fma2(p2[o], wf, x2);
            }
        }
        float2 D0 = up2(d0), D1 = up2(d1), D2 = up2(d2);
        float invA = 1.f / (D0.x * D0.x + D1.x * D1.x + D2.x * D2.x + EPSV);
        float invB = 1.f / (D0.y * D0.y + D1.y * D1.y + D2.y * D2.y + EPSV);
        #pragma unroll
        for (int o = 0; o < OT; o++) {
            float2 P0 = up2(p0[o]), P1 = up2(p1[o]), P2 = up2(p2[o]);
            {
                float dot = P0.x * D0.x + P1.x * D1.x + P2.x * D2.x;
                float s0, s1, s2;
                if (dot >= 0.f) { s0 = P0.x; s1 = P1.x; s2 = P2.x; }
                else {
                    float sc = dot * invA;
                    s0 = P0.x - sc * D0.x; s1 = P1.x - sc * D1.x; s2 = P2.x - sc * D2.x;
                }
                sum[o][0] += 0.2f * P0.x + 0.8f * s0;
                sum[o][1] += 0.2f * P1.x + 0.8f * s1;
                sum[o][2] += 0.2f * P2.x + 0.8f * s2;
            }
            {
                float dot = P0.y * D0.y + P1.y * D1.y + P2.y * D2.y;
                float s0, s1, s2;
                if (dot >= 0.f) { s0 = P0.y; s1 = P1.y; s2 = P2.y; }
                else {
                    float sc = dot * invB;
                    s0 = P0.y - sc * D0.y; s1 = P1.y - sc * D1.y; s2 = P2.y - sc * D2.y;
                }
                sum[o][0] += 0.2f * P0.y + 0.8f * s0;
                sum[o][1] += 0.2f * P1.y + 0.8f * s1;
                sum[o][2] += 0.2f * P2.y + 0.8f * s2;
            }
        }
    }
    #pragma unroll
    for (int o = 0; o < OT; o++)
        #pragma unroll
        for (int dd = 0; dd < 3; dd++) {
            float v = sum[o][dd];
            #pragma unroll
            for (int s = 16; s; s >>= 1) v += __shfl_down_sync(0xffffffffu, v, s);
            if ((tid & 31) == 0) atomicAdd(&sacc[o * 3 + dd], v);
        }
    __syncthreads();
    if (tid < OT * 3) out[b * 1023 + o0 * 3 + tid] = sacc[tid] * (1.f / NPT);
    __syncthreads();
}

// ================= mega kernel =================
#define KT 512
#define YT 256
#define FT 248

__global__ __launch_bounds__(256, 2)
void vn_mega(const float* __restrict__ x,
             const float* __restrict__ Wf0, const float* __restrict__ Wd0,
             const float* __restrict__ Wf1, const float* __restrict__ Wd1,
             const float* __restrict__ Wf2, const float* __restrict__ Wd2,
             const float* __restrict__ Wf3, const float* __restrict__ Wd3,
             const float* __restrict__ Wf4, const float* __restrict__ Wd4,
             float* __restrict__ out)
{
    extern __shared__ float smraw[];
    __shared__ int s_it;
    const float* feat = g_feat;
    int nb = gridDim.x;

    // ---- layer 0 ----
    for (;;) {
        int it = next_tile(0, &s_it);
        if (it >= KT + YT) break;
        if (it < KT) knn_tile<3>(x, 1, 0, it, smraw);
        else         ymap_tile<1, 21>(x, 1, 0, Wf0, Wd0, it - KT, smraw);
    }
    grid_sync(nb);
    for (;;) {
        int it = next_tile(1, &s_it);
        if (it >= (TOTPT + 11) / 12) break;
        pair_tile<21, 12>(0, it);
    }
    grid_sync(nb);

    // ---- layer 1 ----
    for (;;) {
        int it = next_tile(2, &s_it);
        if (it >= KT + YT) break;
        if (it < KT) knn_tile<63>(feat, CTOT, 0, it, smraw);
        else         ymap_tile<21, 21>(feat, CTOT, 0, Wf1, Wd1, it - KT, smraw);
    }
    grid_sync(nb);
    for (;;) {
        int it = next_tile(3, &s_it);
        if (it >= (TOTPT + 11) / 12) break;
        pair_tile<21, 12>(21, it);
    }
    grid_sync(nb);

    // ---- layer 2 ----
    for (;;) {
        int it = next_tile(4, &s_it);
        if (it >= KT + YT) break;
        if (it < KT) knn_tile<63>(feat, CTOT, 21, it, smraw);
        else         ymap_tile<21, 42>(feat, CTOT, 21, Wf2, Wd2, it - KT, smraw);
    }
    grid_sync(nb);
    for (;;) {
        int it = next_tile(5, &s_it);
        if (it >= (TOTPT + 5) / 6) break;
        pair_tile<42, 6>(42, it);
    }
    grid_sync(nb);

    // ---- layer 3 (+ final partial over completed feat[0:84)) ----
    for (;;) {
        int it = next_tile(6, &s_it);
        if (it >= KT + YT + FT) break;
        if (it < KT)           knn_tile<126>(feat, CTOT, 42, it, smraw);
        else if (it < KT + YT) ymap_tile<42, 85>(feat, CTOT, 42, Wf3, Wd3, it - KT, smraw);
        else                   final_part_tile(Wf4, Wd4, it - KT - YT);
    }
    grid_sync(nb);
    for (;;) {
        int it = next_tile(7, &s_it);
        if (it >= (TOTPT + 2) / 3) break;
        pair_tile<85, 3>(84, it);
    }
    grid_sync(nb);

    // ---- final remainder + mean over N ----
    for (;;) {
        int it = next_tile(8, &s_it);
        if (it >= FT) break;
        final_rest_tile(Wf4, Wd4, out, it);
    }

    // reset tickets for next graph replay (all pulls complete after sync)
    grid_sync(nb);
    if (blockIdx.x == 0 && threadIdx.x < 12) g_ticket[threadIdx.x] = 0;
}

// ================= launch =================
extern "C" void kernel_launch(void* const* d_in, const int* in_sizes, int n_in,
                              void* d_out, int out_size)
{
    const float* x   = (const float*)d_in[0];
    const float* Wf0 = (const float*)d_in[1];
    const float* Wd0 = (const float*)d_in[2];
    const float* Wf1 = (const float*)d_in[3];
    const float* Wd1 = (const float*)d_in[4];
    const float* Wf2 = (const float*)d_in[5];
    const float* Wd2 = (const float*)d_in[6];
    const float* Wf3 = (const float*)d_in[7];
    const float* Wd3 = (const float*)d_in[8];
    const float* Wf4 = (const float*)d_in[9];
    const float* Wd4 = (const float*)d_in[10];
    float* out = (float*)d_out;

    static int nblocks = 0;
    static bool init_done = false;
    if (!init_done) {
        int sms = 0;
        cudaDeviceGetAttribute(&sms, cudaDevAttrMultiProcessorCount, 0);
        if (sms <= 0) sms = 148;
        nblocks = 2 * sms;
        cudaFuncSetAttribute(vn_mega, cudaFuncAttributeMaxDynamicSharedMemorySize, DSMEM);
        init_done = true;
    }

    vn_mega<<<nblocks, 256, DSMEM>>>(x, Wf0, Wd0, Wf1, Wd1, Wf2, Wd2,
                                     Wf3, Wd3, Wf4, Wd4, out);
}